// round 5
// baseline (speedup 1.0000x reference)
#include <cuda_runtime.h>
#include <float.h>

// Problem constants: B=32, C=64, H=W=64, code_size=512, BETA=0.25
#define Bn   32
#define Cn   64
#define HWn  4096
#define CBn  512
#define ST_ELEMS  (Bn * Cn * HWn)   // 8388608
#define IDX_ELEMS (Bn * HWn)        // 131072
#define GRID      148
#define NTHREADS  512
#define NWARPS    16
#define TOTWARPS  (GRID * NWARPS)   // 2368
#define NTILES    4096              // 131072 rows / 32 rows-per-tile
// smem: codebook 512*64 floats + cnorm 512 floats
#define SMEMSZ (CBn * Cn * 4 + CBn * 4)

typedef unsigned long long ull;

__device__ float g_blocksums[GRID];
__device__ unsigned int g_done_ctr = 0;

static __device__ __forceinline__ void fma2(ull &acc, ull a, ull b) {
    asm("fma.rn.f32x2 %0, %1, %2, %0;" : "+l"(acc) : "l"(a), "l"(b));
}
static __device__ __forceinline__ ull pack2(float lo, float hi) {
    ull r; asm("mov.b64 %0, {%1, %2};" : "=l"(r) : "f"(lo), "f"(hi)); return r;
}
static __device__ __forceinline__ float2 unpack2(ull v) {
    float2 r; asm("mov.b64 {%0, %1}, %2;" : "=f"(r.x), "=f"(r.y) : "l"(v)); return r;
}

// Persistent kernel: grid=148, 512 threads. Work unit = one 32-row warp tile.
// Tile t: b = t & 31, hw = (t & ~31) + lane. Row n = hw*B + b of the (N, C)
// matrix = inputs[b, :, hw]  (coalesced along hw).
// Warp g (= bid + 148*wid) takes tiles {g, g + 2368} — balanced 6..7 tiles
// per SMSP across the chip.
__global__ void __launch_bounds__(NTHREADS, 1) vq_kernel(
    const float* __restrict__ inp,   // (B, C, H, W)
    const float* __restrict__ cb,    // (512, 64)
    float* __restrict__ out,
    long long out_size)
{
    extern __shared__ float smem[];
    float* scb = smem;              // codebook, row-major 512x64
    float* scn = smem + CBn * Cn;   // per-code squared norms

    const int tid  = threadIdx.x;
    const int wid  = tid >> 5;
    const int lane = tid & 31;

    // Cooperative codebook load into smem (float4).
    for (int i = tid; i < CBn * Cn / 4; i += NTHREADS)
        ((float4*)scb)[i] = ((const float4*)cb)[i];

    // Per-code squared norms (4-lane accumulate + pairwise combine) —
    // identical arithmetic to the passing round-2 kernel.
    for (int j = tid; j < CBn; j += NTHREADS) {
        const float4* r = (const float4*)(cb + j * Cn);
        float sa = 0.f, sb = 0.f, sc = 0.f, sd = 0.f;
        #pragma unroll
        for (int i = 0; i < 16; i++) {
            float4 v = r[i];
            sa = fmaf(v.x, v.x, sa);
            sb = fmaf(v.y, v.y, sb);
            sc = fmaf(v.z, v.z, sc);
            sd = fmaf(v.w, v.w, sd);
        }
        scn[j] = (sa + sb) + (sc + sd);
    }
    __syncthreads();

    float lsum = 0.f;

    const int g = blockIdx.x + GRID * wid;   // global warp id, 0..2367

    for (int t = g; t < NTILES; t += TOTWARPS) {
        const int b  = t & 31;
        const int hw = (t & ~31) + lane;
        const float* __restrict__ rp = inp + (size_t)b * Cn * HWn + hw;

        // Load this row (64 floats) into registers as 32 f32x2 pairs.
        ull x[32];
        #pragma unroll
        for (int i = 0; i < 32; i++)
            x[i] = pack2(rp[(size_t)(2 * i) * HWn],
                         rp[(size_t)(2 * i + 1) * HWn]);

        // Row squared norm — same accumulator split as round 2 (two f32x2
        // accumulators, pairwise combine). Must be included in the distance:
        // the reference quantizes dist at magnitude ~xx, and argmin
        // tie-breaking depends on that quantization.
        ull n0 = 0ULL, n1 = 0ULL;
        #pragma unroll
        for (int i = 0; i < 16; i++) {
            fma2(n0, x[2 * i],     x[2 * i]);
            fma2(n1, x[2 * i + 1], x[2 * i + 1]);
        }
        float2 t0 = unpack2(n0), t1 = unpack2(n1);
        const float xx = (t0.x + t0.y) + (t1.x + t1.y);

        // Argmin over 512 codes: d = (xx - 2*dot) + cn, exactly as reference.
        float best = FLT_MAX;
        int   bj   = 0;

        #pragma unroll 2
        for (int j = 0; j < CBn; j++) {
            const ulonglong2* __restrict__ crow =
                (const ulonglong2*)(scb + j * Cn);
            ull a0 = 0ULL, a1 = 0ULL;
            #pragma unroll
            for (int i = 0; i < 16; i++) {
                ulonglong2 cc = crow[i];   // broadcast LDS.128
                fma2(a0, x[2 * i],     cc.x);
                fma2(a1, x[2 * i + 1], cc.y);
            }
            float2 pa = unpack2(a0), pb = unpack2(a1);
            float dot = (pa.x + pa.y) + (pb.x + pb.y);
            float d = (xx - 2.0f * dot) + scn[j];
            if (d < best) { best = d; bj = j; }
        }

        // Epilogue: gather winning code row from global (L2-resident), write
        // st + index, accumulate loss partial.
        float* st = out + (size_t)b * Cn * HWn + hw;
        const float4* cr = (const float4*)(cb + bj * Cn);
        #pragma unroll
        for (int i = 0; i < 16; i++) {
            float4 v = cr[i];
            float2 xa = unpack2(x[2 * i]);
            float2 xb = unpack2(x[2 * i + 1]);

            st[(size_t)(4 * i + 0) * HWn] = v.x;
            st[(size_t)(4 * i + 1) * HWn] = v.y;
            st[(size_t)(4 * i + 2) * HWn] = v.z;
            st[(size_t)(4 * i + 3) * HWn] = v.w;

            float e;
            e = v.x - xa.x; lsum = fmaf(e, e, lsum);
            e = v.y - xa.y; lsum = fmaf(e, e, lsum);
            e = v.z - xb.x; lsum = fmaf(e, e, lsum);
            e = v.w - xb.y; lsum = fmaf(e, e, lsum);
        }

        long long pidx = (long long)ST_ELEMS + (long long)b * HWn + hw;
        if (pidx < out_size) out[pidx] = (float)bj;
    }

    // Deterministic reduction of loss partials: warp shuffle tree, then
    // fixed-order sums.
    #pragma unroll
    for (int off = 16; off > 0; off >>= 1)
        lsum += __shfl_down_sync(0xffffffffu, lsum, off);
    __shared__ float wsum[NWARPS];
    if (lane == 0) wsum[wid] = lsum;
    __syncthreads();

    __shared__ bool s_last;
    if (tid == 0) {
        float s = 0.f;
        #pragma unroll
        for (int w = 0; w < NWARPS; w++) s += wsum[w];
        g_blocksums[blockIdx.x] = s;
        __threadfence();
        unsigned int prev = atomicAdd(&g_done_ctr, 1u);
        s_last = (prev == GRID - 1);
    }
    __syncthreads();

    // Last block finishes: deterministic double sum, loss = (1+BETA)*MSE.
    if (s_last && tid == 0) {
        __threadfence();
        double s = 0.0;
        for (int i = 0; i < GRID; i++) s += (double)g_blocksums[i];
        double mse = s / (double)ST_ELEMS;
        long long off = (long long)ST_ELEMS + IDX_ELEMS;
        if (off < out_size) out[off] = (float)(1.25 * mse);
        g_done_ctr = 0;   // reset for next graph replay (deterministic)
    }
}

extern "C" void kernel_launch(void* const* d_in, const int* in_sizes, int n_in,
                              void* d_out, int out_size) {
    const float* inp = (const float*)d_in[0];
    const float* cb  = (const float*)d_in[1];
    // Defensive: swap if metadata order differs.
    if (n_in >= 2 && in_sizes[0] == CBn * Cn && in_sizes[1] == ST_ELEMS) {
        const float* t = inp; inp = cb; cb = t;
    }

    cudaFuncSetAttribute(vq_kernel,
                         cudaFuncAttributeMaxDynamicSharedMemorySize, SMEMSZ);

    vq_kernel<<<GRID, NTHREADS, SMEMSZ>>>(inp, cb, (float*)d_out,
                                          (long long)out_size);
}

// round 6
// speedup vs baseline: 1.1416x; 1.1416x over previous
#include <cuda_runtime.h>
#include <float.h>

// Problem constants: B=32, C=64, H=W=64, code_size=512, BETA=0.25
#define Bn   32
#define Cn   64
#define HWn  4096
#define CBn  512
#define ST_ELEMS  (Bn * Cn * HWn)   // 8388608
#define IDX_ELEMS (Bn * HWn)        // 131072
#define GRID      148
#define NTHREADS  256
#define NWARPS    8
#define TOTWARPS  (GRID * NWARPS)   // 1184
#define NUNITS    2048              // 131072 rows / 64 rows-per-unit
// smem: codebook 512*64 floats + cnorm 512 floats
#define SMEMSZ (CBn * Cn * 4 + CBn * 4)

typedef unsigned long long ull;

__device__ float g_blocksums[GRID];
__device__ unsigned int g_done_ctr = 0;

static __device__ __forceinline__ void fma2(ull &acc, ull a, ull b) {
    asm("fma.rn.f32x2 %0, %1, %2, %0;" : "+l"(acc) : "l"(a), "l"(b));
}
static __device__ __forceinline__ ull pack2(float lo, float hi) {
    ull r; asm("mov.b64 %0, {%1, %2};" : "=l"(r) : "f"(lo), "f"(hi)); return r;
}
static __device__ __forceinline__ float2 unpack2(ull v) {
    float2 r; asm("mov.b64 {%0, %1}, %2;" : "=f"(r.x), "=f"(r.y) : "l"(v)); return r;
}

// Persistent kernel: grid=148, 256 threads (8 warps), 2 rows/thread.
// Work unit = 64 rows: unit u -> b = u & 31, hwbase = (u >> 5) * 64.
// Thread handles rows hw0 = hwbase + lane and hw1 = hw0 + 32.
// Warp g = bid + 148*wid takes units {g, g + 1184}.
// LDS:FMA is now 1:1 per code (16 broadcast LDS.128 serve 64 FFMA2).
__global__ void __launch_bounds__(NTHREADS, 1) vq_kernel(
    const float* __restrict__ inp,   // (B, C, H, W)
    const float* __restrict__ cb,    // (512, 64)
    float* __restrict__ out,
    long long out_size)
{
    extern __shared__ float smem[];
    float* scb = smem;              // codebook, row-major 512x64
    float* scn = smem + CBn * Cn;   // per-code squared norms

    const int tid  = threadIdx.x;
    const int wid  = tid >> 5;
    const int lane = tid & 31;

    // Cooperative codebook load into smem (float4).
    for (int i = tid; i < CBn * Cn / 4; i += NTHREADS)
        ((float4*)scb)[i] = ((const float4*)cb)[i];

    // Per-code squared norms (4-lane accumulate + pairwise combine) —
    // identical arithmetic to the passing kernels.
    for (int j = tid; j < CBn; j += NTHREADS) {
        const float4* r = (const float4*)(cb + j * Cn);
        float sa = 0.f, sb = 0.f, sc = 0.f, sd = 0.f;
        #pragma unroll
        for (int i = 0; i < 16; i++) {
            float4 v = r[i];
            sa = fmaf(v.x, v.x, sa);
            sb = fmaf(v.y, v.y, sb);
            sc = fmaf(v.z, v.z, sc);
            sd = fmaf(v.w, v.w, sd);
        }
        scn[j] = (sa + sb) + (sc + sd);
    }
    __syncthreads();

    float lsum = 0.f;

    const int g = blockIdx.x + GRID * wid;   // global warp id, 0..1183

    for (int u = g; u < NUNITS; u += TOTWARPS) {
        const int b   = u & 31;
        const int hw0 = ((u >> 5) << 6) + lane;
        const int hw1 = hw0 + 32;
        const float* __restrict__ rp0 = inp + (size_t)b * Cn * HWn + hw0;
        const float* __restrict__ rp1 = rp0 + 32;

        // Load both rows (64 floats each) as f32x2 pairs.
        ull x0[32], x1[32];
        #pragma unroll
        for (int i = 0; i < 32; i++) {
            x0[i] = pack2(rp0[(size_t)(2 * i) * HWn],
                          rp0[(size_t)(2 * i + 1) * HWn]);
            x1[i] = pack2(rp1[(size_t)(2 * i) * HWn],
                          rp1[(size_t)(2 * i + 1) * HWn]);
        }

        // Row squared norms — same accumulator split as the passing kernels.
        ull n0a = 0ULL, n0b = 0ULL, n1a = 0ULL, n1b = 0ULL;
        #pragma unroll
        for (int i = 0; i < 16; i++) {
            fma2(n0a, x0[2 * i],     x0[2 * i]);
            fma2(n0b, x0[2 * i + 1], x0[2 * i + 1]);
            fma2(n1a, x1[2 * i],     x1[2 * i]);
            fma2(n1b, x1[2 * i + 1], x1[2 * i + 1]);
        }
        float2 t0 = unpack2(n0a), t1 = unpack2(n0b);
        const float xx0 = (t0.x + t0.y) + (t1.x + t1.y);
        float2 t2 = unpack2(n1a), t3 = unpack2(n1b);
        const float xx1 = (t2.x + t2.y) + (t3.x + t3.y);

        // Argmin over 512 codes: d = (xx - 2*dot) + cn, reference-exact form.
        float best0 = FLT_MAX, best1 = FLT_MAX;
        int bj0 = 0, bj1 = 0;

        #pragma unroll 2
        for (int j = 0; j < CBn; j++) {
            const ulonglong2* __restrict__ crow =
                (const ulonglong2*)(scb + j * Cn);
            ull a0 = 0ULL, a1 = 0ULL, c0 = 0ULL, c1 = 0ULL;
            #pragma unroll
            for (int i = 0; i < 16; i++) {
                ulonglong2 cc = crow[i];   // broadcast LDS.128, amortized x2
                fma2(a0, x0[2 * i],     cc.x);
                fma2(a1, x0[2 * i + 1], cc.y);
                fma2(c0, x1[2 * i],     cc.x);
                fma2(c1, x1[2 * i + 1], cc.y);
            }
            float2 pa = unpack2(a0), pb = unpack2(a1);
            float dot0 = (pa.x + pa.y) + (pb.x + pb.y);
            float2 qa = unpack2(c0), qb = unpack2(c1);
            float dot1 = (qa.x + qa.y) + (qb.x + qb.y);

            float cn = scn[j];
            float d0 = (xx0 - 2.0f * dot0) + cn;
            float d1 = (xx1 - 2.0f * dot1) + cn;
            if (d0 < best0) { best0 = d0; bj0 = j; }
            if (d1 < best1) { best1 = d1; bj1 = j; }
        }

        // Epilogue: gather winning code rows from global (L2-resident),
        // write st + indices, accumulate loss partials.
        float* st0 = out + (size_t)b * Cn * HWn + hw0;
        float* st1 = st0 + 32;
        const float4* c0r = (const float4*)(cb + bj0 * Cn);
        const float4* c1r = (const float4*)(cb + bj1 * Cn);
        #pragma unroll
        for (int i = 0; i < 16; i++) {
            float4 v0 = c0r[i];
            float4 v1 = c1r[i];
            float2 xa0 = unpack2(x0[2 * i]);
            float2 xb0 = unpack2(x0[2 * i + 1]);
            float2 xa1 = unpack2(x1[2 * i]);
            float2 xb1 = unpack2(x1[2 * i + 1]);

            st0[(size_t)(4 * i + 0) * HWn] = v0.x;
            st0[(size_t)(4 * i + 1) * HWn] = v0.y;
            st0[(size_t)(4 * i + 2) * HWn] = v0.z;
            st0[(size_t)(4 * i + 3) * HWn] = v0.w;

            st1[(size_t)(4 * i + 0) * HWn] = v1.x;
            st1[(size_t)(4 * i + 1) * HWn] = v1.y;
            st1[(size_t)(4 * i + 2) * HWn] = v1.z;
            st1[(size_t)(4 * i + 3) * HWn] = v1.w;

            float e;
            e = v0.x - xa0.x; lsum = fmaf(e, e, lsum);
            e = v0.y - xa0.y; lsum = fmaf(e, e, lsum);
            e = v0.z - xb0.x; lsum = fmaf(e, e, lsum);
            e = v0.w - xb0.y; lsum = fmaf(e, e, lsum);
            e = v1.x - xa1.x; lsum = fmaf(e, e, lsum);
            e = v1.y - xa1.y; lsum = fmaf(e, e, lsum);
            e = v1.z - xb1.x; lsum = fmaf(e, e, lsum);
            e = v1.w - xb1.y; lsum = fmaf(e, e, lsum);
        }

        long long pidx = (long long)ST_ELEMS + (long long)b * HWn + hw0;
        if (pidx < out_size) out[pidx] = (float)bj0;
        long long pidx1 = pidx + 32;
        if (pidx1 < out_size) out[pidx1] = (float)bj1;
    }

    // Deterministic reduction of loss partials.
    #pragma unroll
    for (int off = 16; off > 0; off >>= 1)
        lsum += __shfl_down_sync(0xffffffffu, lsum, off);
    __shared__ float wsum[NWARPS];
    if (lane == 0) wsum[wid] = lsum;
    __syncthreads();

    __shared__ bool s_last;
    if (tid == 0) {
        float s = 0.f;
        #pragma unroll
        for (int w = 0; w < NWARPS; w++) s += wsum[w];
        g_blocksums[blockIdx.x] = s;
        __threadfence();
        unsigned int prev = atomicAdd(&g_done_ctr, 1u);
        s_last = (prev == GRID - 1);
    }
    __syncthreads();

    // Last block: deterministic double sum, loss = (1+BETA)*MSE.
    if (s_last && tid == 0) {
        __threadfence();
        double s = 0.0;
        for (int i = 0; i < GRID; i++) s += (double)g_blocksums[i];
        double mse = s / (double)ST_ELEMS;
        long long off = (long long)ST_ELEMS + IDX_ELEMS;
        if (off < out_size) out[off] = (float)(1.25 * mse);
        g_done_ctr = 0;   // reset for next graph replay
    }
}

extern "C" void kernel_launch(void* const* d_in, const int* in_sizes, int n_in,
                              void* d_out, int out_size) {
    const float* inp = (const float*)d_in[0];
    const float* cb  = (const float*)d_in[1];
    // Defensive: swap if metadata order differs.
    if (n_in >= 2 && in_sizes[0] == CBn * Cn && in_sizes[1] == ST_ELEMS) {
        const float* t = inp; inp = cb; cb = t;
    }

    cudaFuncSetAttribute(vq_kernel,
                         cudaFuncAttributeMaxDynamicSharedMemorySize, SMEMSZ);

    vq_kernel<<<GRID, NTHREADS, SMEMSZ>>>(inp, cb, (float*)d_out,
                                          (long long)out_size);
}